// round 10
// baseline (speedup 1.0000x reference)
#include <cuda_runtime.h>

#define SEQ 100
#define NF  18
#define HD  16
#define WPC 8        // warps per CTA (256 threads)
#define BPW 4        // batches per warp (all 32 lanes cooperate)
#define L1K 34       // layer-1 rows: 18 x + 16 h1
#define L2K 32       // layer-2 rows: 16 relu(h1) + 16 h2
#define OPSTR 12     // floats per operand row (48B: 16B-aligned, conflict-spread)

typedef unsigned long long u64;

struct __align__(16) Smem {
    float4 w1[L1K][HD];   // rows 0..17: Wih1 cols, rows 18..33: Whh1 cols; [row][j]=(wi,wf,wg,wo)
    float4 w2[L2K][HD];   // rows 0..15: Wih2, rows 16..31: Whh2
    float4 bia1[HD];      // (bi,bf,bg,bo) combined
    float4 bia2[HD];
    float  op1[WPC][L1K][OPSTR];  // rows 0..17: x_t dup (v,v); rows 18..33: h1 dup
    float  op2[WPC][L2K][OPSTR];  // rows 0..15: relu(h1) dup; rows 16..31: h2 dup
};

__device__ __forceinline__ u64 ffma2(u64 a, u64 b, u64 c) {
    u64 d;
    asm("fma.rn.f32x2 %0, %1, %2, %3;" : "=l"(d) : "l"(a), "l"(b), "l"(c));
    return d;
}
__device__ __forceinline__ u64 addf2(u64 a, u64 b) {
    u64 d;
    asm("add.rn.f32x2 %0, %1, %2;" : "=l"(d) : "l"(a), "l"(b));
    return d;
}
__device__ __forceinline__ float2 unpk(u64 v) {
    float2 r;
    asm("mov.b64 {%0, %1}, %2;" : "=f"(r.x), "=f"(r.y) : "l"(v));
    return r;
}
__device__ __forceinline__ float sigf(float x) {
    float e = __expf(-x);
    return __fdividef(1.f, 1.f + e);
}
// overflow-safe tanh
__device__ __forceinline__ float tanhfast(float x) {
    float a = fabsf(x);
    float e = __expf(2.f * a);
    float t = 1.f - __fdividef(2.f, e + 1.f);
    return x < 0.f ? -t : t;
}

// one k-row: weight float4 (1 LDS.128), operand 4 dup batches (2 LDS.128), 8 FFMA2
#define KSTEP(WROW, OPROW) do {                                         \
    ulonglong2 _w  = *(const ulonglong2*)(WROW);                        \
    ulonglong2 _oa = *(const ulonglong2*)(OPROW);                       \
    ulonglong2 _ob = *(const ulonglong2*)((const float*)(OPROW) + 4);   \
    aIF0 = ffma2(_oa.x, _w.x, aIF0);  aGO0 = ffma2(_oa.x, _w.y, aGO0);  \
    aIF1 = ffma2(_oa.y, _w.x, aIF1);  aGO1 = ffma2(_oa.y, _w.y, aGO1);  \
    aIF2 = ffma2(_ob.x, _w.x, aIF2);  aGO2 = ffma2(_ob.x, _w.y, aGO2);  \
    aIF3 = ffma2(_ob.y, _w.x, aIF3);  aGO3 = ffma2(_ob.y, _w.y, aGO3);  \
} while (0)

__global__ void __launch_bounds__(256)
lstm2_kernel(const float* __restrict__ x,
             const float* __restrict__ Wih1, const float* __restrict__ Whh1,
             const float* __restrict__ bih1, const float* __restrict__ bhh1,
             const float* __restrict__ Wih2, const float* __restrict__ Whh2,
             const float* __restrict__ bih2, const float* __restrict__ bhh2,
             float* __restrict__ out)
{
    extern __shared__ Smem sm[];
    Smem& s = sm[0];
    const int tid = threadIdx.x;

    // ---- one-time weight prep: unified row tables, gate-packed float4 ----
    for (int i = tid; i < L1K * HD; i += 256) {
        int row = i / HD, j = i % HD;
        float4 w;
        if (row < NF) {
            int k = row;
            w = make_float4(Wih1[j * NF + k],        Wih1[(16 + j) * NF + k],
                            Wih1[(32 + j) * NF + k], Wih1[(48 + j) * NF + k]);
        } else {
            int k = row - NF;
            w = make_float4(Whh1[j * HD + k],        Whh1[(16 + j) * HD + k],
                            Whh1[(32 + j) * HD + k], Whh1[(48 + j) * HD + k]);
        }
        s.w1[row][j] = w;
    }
    for (int i = tid; i < L2K * HD; i += 256) {
        int row = i / HD, j = i % HD;
        float4 w;
        if (row < HD) {
            int k = row;
            w = make_float4(Wih2[j * HD + k],        Wih2[(16 + j) * HD + k],
                            Wih2[(32 + j) * HD + k], Wih2[(48 + j) * HD + k]);
        } else {
            int k = row - HD;
            w = make_float4(Whh2[j * HD + k],        Whh2[(16 + j) * HD + k],
                            Whh2[(32 + j) * HD + k], Whh2[(48 + j) * HD + k]);
        }
        s.w2[row][j] = w;
    }
    if (tid < HD) {
        int j = tid;
        s.bia1[j] = make_float4(bih1[j] + bhh1[j],           bih1[16 + j] + bhh1[16 + j],
                                bih1[32 + j] + bhh1[32 + j], bih1[48 + j] + bhh1[48 + j]);
        s.bia2[j] = make_float4(bih2[j] + bhh2[j],           bih2[16 + j] + bhh2[16 + j],
                                bih2[32 + j] + bhh2[32 + j], bih2[48 + j] + bhh2[48 + j]);
    }
    __syncthreads();

    const int warp = tid >> 5;
    const int lane = tid & 31;
    const int kh   = lane >> 4;          // k-half: 0 or 1
    const int j    = lane & 15;
    const long warpBatch = (long)(blockIdx.x * WPC + warp) * BPW;
    const float* xbase = x + warpBatch * (long)(SEQ * NF);

    // zero h rows (each thread owns its 16B slot: [row][kh*4..kh*4+3])
    {
        float4 z = make_float4(0.f, 0.f, 0.f, 0.f);
        *(float4*)&s.op1[warp][NF + j][kh * 4] = z;   // h1 dup
        *(float4*)&s.op2[warp][j][kh * 4]      = z;   // relu(h1) dup
        *(float4*)&s.op2[warp][HD + j][kh * 4] = z;   // h2 dup
    }
    // per-thread cell state for its 2 assigned batches (kh0 -> b0,b1; kh1 -> b2,b3)
    float c1a = 0.f, c1b = 0.f, c2a = 0.f, c2b = 0.f;
    float h2a = 0.f, h2b = 0.f;
    __syncwarp();

    // biases: only kh==0 seeds them (kh1 partial starts at 0)
    const u64* bp1 = (const u64*)&s.bia1[j];
    const u64* bp2 = (const u64*)&s.bia2[j];
    const u64 b1if = kh ? 0ull : bp1[0], b1go = kh ? 0ull : bp1[1];
    const u64 b2if = kh ? 0ull : bp2[0], b2go = kh ? 0ull : bp2[1];

    const int r1 = kh * 17;   // phase-A row base (17 rows per half)
    const int r2 = kh * 16;   // phase-B row base (16 rows per half)

    for (int t = 0; t < SEQ; t++) {
        // ---- stage x_t: 18 rows x 4 batches, duplicated ----
        __syncwarp();    // prior phase-A reads of x rows complete
        for (int idx = lane; idx < BPW * NF; idx += 32) {
            int b = idx / NF, k = idx % NF;
            float v = xbase[(long)b * (SEQ * NF) + t * NF + k];
            *(float2*)&s.op1[warp][k][b * 2] = make_float2(v, v);
        }
        __syncwarp();

        // ================= phase A: layer-1 (this half: 17 rows) =================
        u64 aIF0 = b1if, aIF1 = b1if, aIF2 = b1if, aIF3 = b1if;
        u64 aGO0 = b1go, aGO1 = b1go, aGO2 = b1go, aGO3 = b1go;
#pragma unroll
        for (int i = 0; i < 17; i++)
            KSTEP(&s.w1[r1 + i][j], &s.op1[warp][r1 + i][0]);

        // butterfly-reduce across k-halves (f32x2 adds)
        aIF0 = addf2(aIF0, __shfl_xor_sync(0xffffffffu, aIF0, 16));
        aGO0 = addf2(aGO0, __shfl_xor_sync(0xffffffffu, aGO0, 16));
        aIF1 = addf2(aIF1, __shfl_xor_sync(0xffffffffu, aIF1, 16));
        aGO1 = addf2(aGO1, __shfl_xor_sync(0xffffffffu, aGO1, 16));
        aIF2 = addf2(aIF2, __shfl_xor_sync(0xffffffffu, aIF2, 16));
        aGO2 = addf2(aGO2, __shfl_xor_sync(0xffffffffu, aGO2, 16));
        aIF3 = addf2(aIF3, __shfl_xor_sync(0xffffffffu, aIF3, 16));
        aGO3 = addf2(aGO3, __shfl_xor_sync(0xffffffffu, aGO3, 16));

        // this thread's 2 batches: kh0 -> (0,1), kh1 -> (2,3)
        {
            u64 sIFa = kh ? aIF2 : aIF0, sGOa = kh ? aGO2 : aGO0;
            u64 sIFb = kh ? aIF3 : aIF1, sGOb = kh ? aGO3 : aGO1;
            float2 via = unpk(sIFa), vga = unpk(sGOa);
            float2 vib = unpk(sIFb), vgb = unpk(sGOb);
            float iga = sigf(via.x), fga = sigf(via.y);
            float gga = tanhfast(vga.x), oga = sigf(vga.y);
            float ca = fmaf(fga, c1a, iga * gga);
            c1a = ca;
            float h1a = oga * tanhfast(ca);
            float igb = sigf(vib.x), fgb = sigf(vib.y);
            float ggb = tanhfast(vgb.x), ogb = sigf(vgb.y);
            float cb = fmaf(fgb, c1b, igb * ggb);
            c1b = cb;
            float h1b = ogb * tanhfast(cb);

            __syncwarp();   // all lanes done reading old h1/h2 rows
            *(float4*)&s.op1[warp][NF + j][kh * 4] =
                make_float4(h1a, h1a, h1b, h1b);
            float ra = fmaxf(h1a, 0.f), rb = fmaxf(h1b, 0.f);
            *(float4*)&s.op2[warp][j][kh * 4] =
                make_float4(ra, ra, rb, rb);
        }
        __syncwarp();       // new h1 / relu(h1) visible

        // ================= phase B: layer-2 (this half: 16 rows) =================
        aIF0 = b2if; aIF1 = b2if; aIF2 = b2if; aIF3 = b2if;
        aGO0 = b2go; aGO1 = b2go; aGO2 = b2go; aGO3 = b2go;
#pragma unroll
        for (int i = 0; i < 16; i++)
            KSTEP(&s.w2[r2 + i][j], &s.op2[warp][r2 + i][0]);

        aIF0 = addf2(aIF0, __shfl_xor_sync(0xffffffffu, aIF0, 16));
        aGO0 = addf2(aGO0, __shfl_xor_sync(0xffffffffu, aGO0, 16));
        aIF1 = addf2(aIF1, __shfl_xor_sync(0xffffffffu, aIF1, 16));
        aGO1 = addf2(aGO1, __shfl_xor_sync(0xffffffffu, aGO1, 16));
        aIF2 = addf2(aIF2, __shfl_xor_sync(0xffffffffu, aIF2, 16));
        aGO2 = addf2(aGO2, __shfl_xor_sync(0xffffffffu, aGO2, 16));
        aIF3 = addf2(aIF3, __shfl_xor_sync(0xffffffffu, aIF3, 16));
        aGO3 = addf2(aGO3, __shfl_xor_sync(0xffffffffu, aGO3, 16));

        {
            u64 sIFa = kh ? aIF2 : aIF0, sGOa = kh ? aGO2 : aGO0;
            u64 sIFb = kh ? aIF3 : aIF1, sGOb = kh ? aGO3 : aGO1;
            float2 via = unpk(sIFa), vga = unpk(sGOa);
            float2 vib = unpk(sIFb), vgb = unpk(sGOb);
            float iga = sigf(via.x), fga = sigf(via.y);
            float gga = tanhfast(vga.x), oga = sigf(vga.y);
            float ca = fmaf(fga, c2a, iga * gga);
            c2a = ca;
            h2a = oga * tanhfast(ca);
            float igb = sigf(vib.x), fgb = sigf(vib.y);
            float ggb = tanhfast(vgb.x), ogb = sigf(vgb.y);
            float cb = fmaf(fgb, c2b, igb * ggb);
            c2b = cb;
            h2b = ogb * tanhfast(cb);

            __syncwarp();   // all lanes done reading old h2 rows
            *(float4*)&s.op2[warp][HD + j][kh * 4] =
                make_float4(h2a, h2a, h2b, h2b);
        }
        __syncwarp();       // new h2 visible
    }

    // ---- output: relu(h2_last), [B, 16]; this thread's 2 batches ----
    out[(warpBatch + kh * 2 + 0) * HD + j] = fmaxf(h2a, 0.f);
    out[(warpBatch + kh * 2 + 1) * HD + j] = fmaxf(h2b, 0.f);
}

extern "C" void kernel_launch(void* const* d_in, const int* in_sizes, int n_in,
                              void* d_out, int out_size)
{
    const float* x    = (const float*)d_in[0];
    const float* Wih1 = (const float*)d_in[1];
    const float* Whh1 = (const float*)d_in[2];
    const float* bih1 = (const float*)d_in[3];
    const float* bhh1 = (const float*)d_in[4];
    const float* Wih2 = (const float*)d_in[5];
    const float* Whh2 = (const float*)d_in[6];
    const float* bih2 = (const float*)d_in[7];
    const float* bhh2 = (const float*)d_in[8];
    float* out = (float*)d_out;

    const int smem = (int)sizeof(Smem);   // ~42.7 KB
    cudaFuncSetAttribute(lstm2_kernel,
                         cudaFuncAttributeMaxDynamicSharedMemorySize, smem);

    // 16384 batch / (8 warps * 4 batch) = 512 CTAs of 256 threads
    // -> 4096 warps total, ~28 warps/SM (2x previous)
    lstm2_kernel<<<512, 256, smem>>>(x, Wih1, Whh1, bih1, bhh1,
                                     Wih2, Whh2, bih2, bhh2, out);
}

// round 11
// speedup vs baseline: 1.2937x; 1.2937x over previous
#include <cuda_runtime.h>

#define SEQ 100
#define NF  18
#define HD  16
#define TCH 2        // timesteps staged per chunk
#define WPC 2        // warps per CTA (64 threads)
#define BPW 8        // batches per warp (4 per half)

typedef unsigned long long u64;

struct __align__(16) Smem {
    float4 w1[NF + HD][HD];   // rows 0..17: Wih1, rows 18..33: Whh1; [row][j]=(wi,wf,wg,wo)
    float4 w2[HD + HD][HD];   // rows 0..15: Wih2, rows 16..31: Whh2
    float4 bia1[HD];          // (bi,bf,bg,bo) combined bias
    float4 bia2[HD];
    float  xs [WPC][TCH][NF][BPW];  // batch-packed x, NON-duplicated [k][b]
    float  h1d[WPC][HD][BPW];       // batch-packed h1 (pre-relu, recurrence)
    float  h1r[WPC][HD][BPW];       // batch-packed relu(h1) (layer-2 input)
    float  h2d[WPC][HD][BPW];       // batch-packed h2
};

__device__ __forceinline__ u64 ffma2(u64 a, u64 b, u64 c) {
    u64 d;
    asm("fma.rn.f32x2 %0, %1, %2, %3;" : "=l"(d) : "l"(a), "l"(b), "l"(c));
    return d;
}
__device__ __forceinline__ u64 dup2(float v) {
    u64 d;
    asm("mov.b64 %0, {%1, %1};" : "=l"(d) : "f"(v));
    return d;
}
__device__ __forceinline__ float2 unpk(u64 v) {
    float2 r;
    asm("mov.b64 {%0, %1}, %2;" : "=f"(r.x), "=f"(r.y) : "l"(v));
    return r;
}
__device__ __forceinline__ float sigf(float x) {
    float e = __expf(-x);
    return __fdividef(1.f, 1.f + e);
}
// overflow-safe tanh: tanh(x) = sign(x) * (1 - 2/(exp(2|x|)+1))
__device__ __forceinline__ float tanhfast(float x) {
    float a = fabsf(x);
    float e = __expf(2.f * a);
    float t = 1.f - __fdividef(2.f, e + 1.f);
    return x < 0.f ? -t : t;
}

// one k-row for a named accumulator set:
//   1 LDS.128 weight (non-dup, gate-packed), 4 ALU dups, 1 LDS.128 operand
//   (non-dup, 4 batches), 8 FFMA2
#define KSTEP(AI0,AI1,AF0,AF1,AG0,AG1,AO0,AO1, WPTR, OPPTR) do {        \
    float4 _w = *(const float4*)(WPTR);                                 \
    u64 _wi = dup2(_w.x), _wf = dup2(_w.y);                             \
    u64 _wg = dup2(_w.z), _wo = dup2(_w.w);                             \
    ulonglong2 _o = *(const ulonglong2*)(OPPTR);                        \
    AI0 = ffma2(_o.x, _wi, AI0);  AI1 = ffma2(_o.y, _wi, AI1);          \
    AF0 = ffma2(_o.x, _wf, AF0);  AF1 = ffma2(_o.y, _wf, AF1);          \
    AG0 = ffma2(_o.x, _wg, AG0);  AG1 = ffma2(_o.y, _wg, AG1);          \
    AO0 = ffma2(_o.x, _wo, AO0);  AO1 = ffma2(_o.y, _wo, AO1);          \
} while (0)

__global__ void __launch_bounds__(64, 7)
lstm2_kernel(const float* __restrict__ x,
             const float* __restrict__ Wih1, const float* __restrict__ Whh1,
             const float* __restrict__ bih1, const float* __restrict__ bhh1,
             const float* __restrict__ Wih2, const float* __restrict__ Whh2,
             const float* __restrict__ bih2, const float* __restrict__ bhh2,
             float* __restrict__ out)
{
    extern __shared__ Smem sm[];
    Smem& s = sm[0];
    const int tid = threadIdx.x;

    // ---- one-time weight prep: gate-packed [row][j] float4 ----
    for (int i = tid; i < (NF + HD) * HD; i += 64) {
        int row = i / HD, j = i % HD;
        float4 w;
        if (row < NF) {
            int k = row;
            w = make_float4(Wih1[j * NF + k],        Wih1[(16 + j) * NF + k],
                            Wih1[(32 + j) * NF + k], Wih1[(48 + j) * NF + k]);
        } else {
            int k = row - NF;
            w = make_float4(Whh1[j * HD + k],        Whh1[(16 + j) * HD + k],
                            Whh1[(32 + j) * HD + k], Whh1[(48 + j) * HD + k]);
        }
        s.w1[row][j] = w;
    }
    for (int i = tid; i < 2 * HD * HD; i += 64) {
        int row = i / HD, j = i % HD;
        float4 w;
        if (row < HD) {
            int k = row;
            w = make_float4(Wih2[j * HD + k],        Wih2[(16 + j) * HD + k],
                            Wih2[(32 + j) * HD + k], Wih2[(48 + j) * HD + k]);
        } else {
            int k = row - HD;
            w = make_float4(Whh2[j * HD + k],        Whh2[(16 + j) * HD + k],
                            Whh2[(32 + j) * HD + k], Whh2[(48 + j) * HD + k]);
        }
        s.w2[row][j] = w;
    }
    if (tid < HD) {
        int j = tid;
        s.bia1[j] = make_float4(bih1[j] + bhh1[j],           bih1[16 + j] + bhh1[16 + j],
                                bih1[32 + j] + bhh1[32 + j], bih1[48 + j] + bhh1[48 + j]);
        s.bia2[j] = make_float4(bih2[j] + bhh2[j],           bih2[16 + j] + bhh2[16 + j],
                                bih2[32 + j] + bhh2[32 + j], bih2[48 + j] + bhh2[48 + j]);
    }
    __syncthreads();

    const int warp = tid >> 5;
    const int lane = tid & 31;
    const int half = lane >> 4;
    const int j    = lane & 15;
    const int b0   = half * 4;          // this half's batch offset within warp
    const long warpBatch = (long)(blockIdx.x * WPC + warp) * BPW;
    const float* xbase = x + warpBatch * (long)(SEQ * NF);

    // zero h-state (each thread owns [j][b0..b0+3], 16B)
    {
        float4 z = make_float4(0.f, 0.f, 0.f, 0.f);
        *(float4*)&s.h1d[warp][j][b0] = z;
        *(float4*)&s.h1r[warp][j][b0] = z;
        *(float4*)&s.h2d[warp][j][b0] = z;
    }
    float c1[4] = {0.f, 0.f, 0.f, 0.f};
    float c2[4] = {0.f, 0.f, 0.f, 0.f};
    float h2v[4] = {0.f, 0.f, 0.f, 0.f};
    __syncwarp();

    // duplicated bias registers (seed values for both batch-pairs)
    float4 bv1 = s.bia1[j];
    float4 bv2 = s.bia2[j];
    const u64 BI1 = dup2(bv1.x), BF1 = dup2(bv1.y), BG1 = dup2(bv1.z), BO1 = dup2(bv1.w);
    const u64 BI2 = dup2(bv2.x), BF2 = dup2(bv2.y), BG2 = dup2(bv2.z), BO2 = dup2(bv2.w);

    for (int t = 0; t < SEQ; t++) {
        const int tt = t & (TCH - 1);
        if (tt == 0) {
            __syncwarp();     // previous xs reads complete before overwrite
            // stage TCH steps of x for this warp's 8 batches, batch-packed (no dup)
            for (int idx = lane; idx < TCH * BPW * NF; idx += 32) {
                int k  = idx % NF;
                int r  = idx / NF;        // tc*8 + b
                int b  = r & 7;
                int tc = r >> 3;
                s.xs[warp][tc][k][b] =
                    xbase[(long)b * (SEQ * NF) + (t + tc) * NF + k];
            }
            __syncwarp();
        }

        // ====== merged barrier-free region: layer-1 full + layer-2 recurrent ======
        u64 aI0 = BI1, aI1 = BI1, aF0 = BF1, aF1 = BF1;
        u64 aG0 = BG1, aG1 = BG1, aO0 = BO1, aO1 = BO1;
        u64 bI0 = BI2, bI1 = BI2, bF0 = BF2, bF1 = BF2;
        u64 bG0 = BG2, bG1 = BG2, bO0 = BO2, bO1 = BO2;

#pragma unroll
        for (int k = 0; k < NF; k++)
            KSTEP(aI0,aI1,aF0,aF1,aG0,aG1,aO0,aO1,
                  &s.w1[k][j], &s.xs[warp][tt][k][b0]);
#pragma unroll
        for (int k = 0; k < HD; k++) {
            KSTEP(aI0,aI1,aF0,aF1,aG0,aG1,aO0,aO1,
                  &s.w1[NF + k][j], &s.h1d[warp][k][b0]);
            KSTEP(bI0,bI1,bF0,bF1,bG0,bG1,bO0,bO1,
                  &s.w2[HD + k][j], &s.h2d[warp][k][b0]);
        }

        // ---- layer-1 activations (4 batches) ----
        float h1v[4];
        {
            float2 vi0 = unpk(aI0), vi1 = unpk(aI1);
            float2 vf0 = unpk(aF0), vf1 = unpk(aF1);
            float2 vg0 = unpk(aG0), vg1 = unpk(aG1);
            float2 vo0 = unpk(aO0), vo1 = unpk(aO1);
            float iv[4] = {vi0.x, vi0.y, vi1.x, vi1.y};
            float fv[4] = {vf0.x, vf0.y, vf1.x, vf1.y};
            float gv[4] = {vg0.x, vg0.y, vg1.x, vg1.y};
            float ov[4] = {vo0.x, vo0.y, vo1.x, vo1.y};
#pragma unroll
            for (int p = 0; p < 4; p++) {
                float ig = sigf(iv[p]), fg = sigf(fv[p]);
                float gg = tanhfast(gv[p]), og = sigf(ov[p]);
                float c = fmaf(fg, c1[p], ig * gg);
                c1[p] = c;
                h1v[p] = og * tanhfast(c);
            }
        }
        __syncwarp();   // all lanes done reading old h1d / h2d
        *(float4*)&s.h1d[warp][j][b0] = make_float4(h1v[0], h1v[1], h1v[2], h1v[3]);
        *(float4*)&s.h1r[warp][j][b0] = make_float4(fmaxf(h1v[0], 0.f), fmaxf(h1v[1], 0.f),
                                                    fmaxf(h1v[2], 0.f), fmaxf(h1v[3], 0.f));
        __syncwarp();   // new h1 visible

        // ====== layer-2 input part (W_ih2 * relu(h1(t))) ======
#pragma unroll
        for (int k = 0; k < HD; k++)
            KSTEP(bI0,bI1,bF0,bF1,bG0,bG1,bO0,bO1,
                  &s.w2[k][j], &s.h1r[warp][k][b0]);

        // ---- layer-2 activations ----
        {
            float2 vi0 = unpk(bI0), vi1 = unpk(bI1);
            float2 vf0 = unpk(bF0), vf1 = unpk(bF1);
            float2 vg0 = unpk(bG0), vg1 = unpk(bG1);
            float2 vo0 = unpk(bO0), vo1 = unpk(bO1);
            float iv[4] = {vi0.x, vi0.y, vi1.x, vi1.y};
            float fv[4] = {vf0.x, vf0.y, vf1.x, vf1.y};
            float gv[4] = {vg0.x, vg0.y, vg1.x, vg1.y};
            float ov[4] = {vo0.x, vo0.y, vo1.x, vo1.y};
#pragma unroll
            for (int p = 0; p < 4; p++) {
                float ig = sigf(iv[p]), fg = sigf(fv[p]);
                float gg = tanhfast(gv[p]), og = sigf(ov[p]);
                float c = fmaf(fg, c2[p], ig * gg);
                c2[p] = c;
                h2v[p] = og * tanhfast(c);
            }
        }
        __syncwarp();   // all lanes done reading old h2d
        *(float4*)&s.h2d[warp][j][b0] = make_float4(h2v[0], h2v[1], h2v[2], h2v[3]);
        __syncwarp();   // new h2 visible
    }

    // ---- output: relu(h2_last), [B, 16] ----
#pragma unroll
    for (int p = 0; p < 4; p++) {
        out[(warpBatch + b0 + p) * HD + j] = fmaxf(h2v[p], 0.f);
    }
}

extern "C" void kernel_launch(void* const* d_in, const int* in_sizes, int n_in,
                              void* d_out, int out_size)
{
    const float* x    = (const float*)d_in[0];
    const float* Wih1 = (const float*)d_in[1];
    const float* Whh1 = (const float*)d_in[2];
    const float* bih1 = (const float*)d_in[3];
    const float* bhh1 = (const float*)d_in[4];
    const float* Wih2 = (const float*)d_in[5];
    const float* Whh2 = (const float*)d_in[6];
    const float* bih2 = (const float*)d_in[7];
    const float* bhh2 = (const float*)d_in[8];
    float* out = (float*)d_out;

    const int smem = (int)sizeof(Smem);   // ~22.9 KB -> 7 CTAs/SM
    cudaFuncSetAttribute(lstm2_kernel,
                         cudaFuncAttributeMaxDynamicSharedMemorySize, smem);

    // 16384 batch / (2 warps * 8 batch) = 1024 CTAs of 64 threads
    lstm2_kernel<<<1024, 64, smem>>>(x, Wih1, Whh1, bih1, bhh1,
                                     Wih2, Whh2, bih2, bhh2, out);
}